// round 2
// baseline (speedup 1.0000x reference)
#include <cuda_runtime.h>
#include <math.h>

#define LL     1632
#define KK     12
#define NUP    8
#define NB     32
#define NA     64
#define RED    408
#define NBLK   136
#define HALFN  817        // mirror table length (n = 0..816)
#define WTN    (10*HALFN) // 8170

// ---------------- scratch (device globals; no allocation allowed) -------------
__device__ float2 g_wtab[WTN];       // cos/sin(2*pi*n*o/L), o=1..10, n=0..816
__device__ float2 g_phtab[LL];       // e^{2*pi*i*q/L}
__device__ float2 g_b12[12];         // e^{2*pi*i*r/12}
__device__ int    g_m[NUP*NB];       // per (u,b) peak position m
__device__ float  g_W[NUP*NB*144];   // per (u,b) 12x12 Wiener matrix
__device__ float  g_win[1024*21];    // per-block partial windows
__device__ float  g_noise[1024];     // per-block partial noise sums

// ---------------- kernel P: build twiddle tables -----------------------------
__global__ void kP() {
    int i = blockIdx.x * blockDim.x + threadIdx.x;
    const double TP = 6.283185307179586476925286766559;
    if (i < WTN) {
        int o = i / HALFN + 1;
        int n = i % HALFN;
        double ang = TP * (double)(n * o) / (double)LL;
        g_wtab[i] = make_float2((float)cos(ang), (float)sin(ang));
    }
    if (i < LL) {
        double ang = TP * (double)i / (double)LL;
        g_phtab[i] = make_float2((float)cos(ang), (float)sin(ang));
    }
    if (i < 12) {
        double ang = TP * (double)i / 12.0;
        g_b12[i] = make_float2((float)cos(ang), (float)sin(ang));
    }
}

// ---------------- kernel A: 21-bin DFT window power + noise ------------------
__device__ __forceinline__ float wred(float v) {
    #pragma unroll
    for (int off = 16; off; off >>= 1) v += __shfl_xor_sync(0xffffffffu, v, off);
    return v;
}

__global__ __launch_bounds__(256, 2) void kA(const float* __restrict__ lsr,
                                             const float* __restrict__ lsi,
                                             const int*   __restrict__ cs) {
    extern __shared__ float smemA[];
    float2* wt  = (float2*)smemA;        // 8170 float2
    float2* b12 = wt + WTN;              // 12 float2
    float*  win = (float*)(b12 + 12);    // 22 floats (21 window + 1 noise)

    const int tid  = threadIdx.x;
    const int bid  = blockIdx.x;
    const int part = bid & 3;
    const int ub   = bid >> 2;
    const int u    = ub >> 5;

    for (int i = tid; i < WTN; i += 256) wt[i] = g_wtab[i];
    if (tid < 12) b12[tid] = g_b12[tid];
    if (tid < 22) win[tid] = 0.f;
    __syncthreads();

    int k12 = (12 - (cs[u] % 12)) % 12; if (k12 < 0) k12 += 12;

    const int lane = tid & 31;
    const int warp = tid >> 5;
    const int a0   = part * 16 + warp * 2;
    const int base0 = (ub * 64 + a0) * LL;   // fits int (max ~26.7M)
    const int base1 = base0 + LL;

    float A0[10], B0[10], C0[10], D0[10];
    float A1[10], B1[10], C1[10], D1[10];
    #pragma unroll
    for (int o = 0; o < 10; ++o) {
        A0[o]=B0[o]=C0[o]=D0[o]=0.f;
        A1[o]=B1[o]=C1[o]=D1[o]=0.f;
    }
    float s0r=0.f, s0i=0.f, s1r=0.f, s1i=0.f, nacc=0.f;

    // r12 tracks (n * k12) mod 12 ; b12[r] = e^{2*pi*i*r/12}  (k12 enters via index)
    int r12  = (lane * k12) % 12;
    int st12 = ((k12 << 5) % 12);

    for (int k = 0; k < 51; ++k) {
        const int n = lane + (k << 5);
        float x0r = lsr[base0 + n], x0i = lsi[base0 + n];
        float x1r = lsr[base1 + n], x1i = lsi[base1 + n];
        if (n < LL - 1) {
            float d0r = lsr[base0 + n + 1] - x0r, d0i = lsi[base0 + n + 1] - x0i;
            float d1r = lsr[base1 + n + 1] - x1r, d1i = lsi[base1 + n + 1] - x1i;
            nacc += d0r*d0r + d0i*d0i + d1r*d1r + d1i*d1i;
        }
        float2 bb = b12[r12];
        r12 += st12; if (r12 >= 12) r12 -= 12;
        float g0r = x0r*bb.x - x0i*bb.y, g0i = x0r*bb.y + x0i*bb.x;
        float g1r = x1r*bb.x - x1i*bb.y, g1i = x1r*bb.y + x1i*bb.x;
        s0r += g0r; s0i += g0i; s1r += g1r; s1i += g1i;

        if (n <= 816) {
            #pragma unroll
            for (int o = 0; o < 10; ++o) {
                float2 c2 = wt[o * HALFN + n];
                A0[o] = fmaf(g0r, c2.x, A0[o]); B0[o] = fmaf(g0r, c2.y, B0[o]);
                C0[o] = fmaf(g0i, c2.x, C0[o]); D0[o] = fmaf(g0i, c2.y, D0[o]);
                A1[o] = fmaf(g1r, c2.x, A1[o]); B1[o] = fmaf(g1r, c2.y, B1[o]);
                C1[o] = fmaf(g1i, c2.x, C1[o]); D1[o] = fmaf(g1i, c2.y, D1[o]);
            }
        } else {
            const int nm = LL - n;   // sin(n) = -sin(nm), cos(n) = cos(nm)
            #pragma unroll
            for (int o = 0; o < 10; ++o) {
                float2 c2 = wt[o * HALFN + nm];
                A0[o] = fmaf(g0r,  c2.x, A0[o]); B0[o] = fmaf(-g0r, c2.y, B0[o]);
                C0[o] = fmaf(g0i,  c2.x, C0[o]); D0[o] = fmaf(-g0i, c2.y, D0[o]);
                A1[o] = fmaf(g1r,  c2.x, A1[o]); B1[o] = fmaf(-g1r, c2.y, B1[o]);
                C1[o] = fmaf(g1i,  c2.x, C1[o]); D1[o] = fmaf(-g1i, c2.y, D1[o]);
            }
        }
    }

    // warp-reduce everything (all lanes end with full sums)
    #pragma unroll
    for (int o = 0; o < 10; ++o) {
        A0[o]=wred(A0[o]); B0[o]=wred(B0[o]); C0[o]=wred(C0[o]); D0[o]=wred(D0[o]);
        A1[o]=wred(A1[o]); B1[o]=wred(B1[o]); C1[o]=wred(C1[o]); D1[o]=wred(D1[o]);
    }
    s0r=wred(s0r); s0i=wred(s0i); s1r=wred(s1r); s1i=wred(s1i); nacc=wred(nacc);

    if (lane == 0) {
        atomicAdd(&win[10], s0r*s0r + s0i*s0i + s1r*s1r + s1i*s1i);
        #pragma unroll
        for (int o = 0; o < 10; ++o) {
            // +(o+1) bin at index 11+o ; -(o+1) bin at index 9-o
            float rp0 = A0[o]-D0[o], ip0 = B0[o]+C0[o];
            float rp1 = A1[o]-D1[o], ip1 = B1[o]+C1[o];
            atomicAdd(&win[11+o], rp0*rp0 + ip0*ip0 + rp1*rp1 + ip1*ip1);
            float rm0 = A0[o]+D0[o], im0 = C0[o]-B0[o];
            float rm1 = A1[o]+D1[o], im1 = C1[o]-B1[o];
            atomicAdd(&win[9-o],  rm0*rm0 + im0*im0 + rm1*rm1 + im1*im1);
        }
        atomicAdd(&win[21], nacc);
    }
    __syncthreads();
    if (tid < 21) g_win[bid * 21 + tid] = win[tid];
    if (tid == 21) g_noise[bid] = win[21];
}

// ---------------- kernel S: argmax + 12x12 Wiener solve per (u,b) ------------
__global__ void kS(const int* __restrict__ cs) {
    __shared__ float win[21];
    __shared__ float Cm[144], Am[144], Iv[144];
    __shared__ float s_sh;

    const int ub = blockIdx.x;
    const int tid = threadIdx.x;           // 144 threads
    const int u = ub >> 5;
    const int i = tid / 12, j = tid % 12;

    if (tid < 21) {
        float s = 0.f;
        #pragma unroll
        for (int p = 0; p < 4; ++p) s += g_win[(ub * 4 + p) * 21 + tid];
        win[tid] = s;
    }
    if (tid == 21) {
        float s = 0.f;
        #pragma unroll
        for (int p = 0; p < 4; ++p) s += g_noise[ub * 4 + p];
        s_sh = s / (64.0f * 1631.0f * 2.0f);
    }
    __syncthreads();

    if (tid == 0) {
        int bi = 0; float bv = win[0];
        for (int q = 1; q < 21; ++q) if (win[q] > bv) { bv = win[q]; bi = q; }
        int k12 = (12 - (cs[u] % 12)) % 12; if (k12 < 0) k12 += 12;
        g_m[ub] = k12 * 136 + (bi - 10);
    }

    int d = i - j; if (d < 0) d = -d;
    float c = (float)pow(0.9, (double)d);
    Cm[tid] = c;
    Am[tid] = c + ((i == j) ? s_sh : 0.f);
    Iv[tid] = (i == j) ? 1.f : 0.f;
    __syncthreads();

    for (int k = 0; k < 12; ++k) {
        float piv = Am[k * 12 + k];
        __syncthreads();
        if (i == k) {
            float ip = 1.0f / piv;
            Am[tid] *= ip; Iv[tid] *= ip;
        }
        __syncthreads();
        float f   = Am[i * 12 + k];
        float akj = Am[k * 12 + j];
        float ikj = Iv[k * 12 + j];
        __syncthreads();
        if (i != k) {
            Am[tid] = fmaf(-f, akj, Am[tid]);
            Iv[tid] = fmaf(-f, ikj, Iv[tid]);
        }
        __syncthreads();
    }

    float w = 0.f;
    #pragma unroll
    for (int k2 = 0; k2 < 12; ++k2) w = fmaf(Cm[i * 12 + k2], Iv[k2 * 12 + j], w);
    g_W[ub * 144 + tid] = w;
}

// ---------------- kernel B: phase shift + avg + interp + W apply -------------
__global__ __launch_bounds__(256) void kB(const float* __restrict__ lsr,
                                          const float* __restrict__ lsi,
                                          float2* __restrict__ out) {
    __shared__ float2 havg[RED];
    __shared__ float2 hint[LL];
    __shared__ float  Ws[144];

    const int row = blockIdx.x;           // (u,b,a) row, 0..16383
    const int ub  = row >> 6;
    const int tid = threadIdx.x;

    if (tid < 144) Ws[tid] = g_W[ub * 144 + tid];
    const int m  = g_m[ub];
    const int mm = ((m % LL) + LL) % LL;
    const int base = row * LL;

    // stage 1: phase-shifted 4-tap average -> havg[408]
    for (int r = tid; r < RED; r += 256) {
        const float4 xr = *(const float4*)(lsr + base + 4 * r);
        const float4 xi = *(const float4*)(lsi + base + 4 * r);
        int q = (mm * (4 * r)) % LL;
        float sr = 0.f, si = 0.f;
        {
            float2 ph = g_phtab[q];
            sr = fmaf(xr.x, ph.x, sr); sr = fmaf(-xi.x, ph.y, sr);
            si = fmaf(xr.x, ph.y, si); si = fmaf( xi.x, ph.x, si);
        }
        q += mm; if (q >= LL) q -= LL;
        {
            float2 ph = g_phtab[q];
            sr = fmaf(xr.y, ph.x, sr); sr = fmaf(-xi.y, ph.y, sr);
            si = fmaf(xr.y, ph.y, si); si = fmaf( xi.y, ph.x, si);
        }
        q += mm; if (q >= LL) q -= LL;
        {
            float2 ph = g_phtab[q];
            sr = fmaf(xr.z, ph.x, sr); sr = fmaf(-xi.z, ph.y, sr);
            si = fmaf(xr.z, ph.y, si); si = fmaf( xi.z, ph.x, si);
        }
        q += mm; if (q >= LL) q -= LL;
        {
            float2 ph = g_phtab[q];
            sr = fmaf(xr.w, ph.x, sr); sr = fmaf(-xi.w, ph.y, sr);
            si = fmaf(xr.w, ph.y, si); si = fmaf( xi.w, ph.x, si);
        }
        havg[r] = make_float2(sr * 0.25f, si * 0.25f);
    }
    __syncthreads();

    // stage 2: linear interpolation -> hint[1632]
    for (int t = tid; t < LL; t += 256) {
        float p = ((float)t - 1.5f) * 0.25f;
        p = fminf(fmaxf(p, 0.f), 407.f);
        int i0 = (int)p; if (i0 > 406) i0 = 406;
        float fr = p - (float)i0;
        float w0 = 1.f - fr;
        float2 a = havg[i0], b = havg[i0 + 1];
        hint[t] = make_float2(a.x * w0 + b.x * fr, a.y * w0 + b.y * fr);
    }
    __syncthreads();

    // stage 3: blockwise W apply (136 blocks x 12, split into half-rows)
    for (int item = tid; item < 272; item += 256) {
        const int blk = item >> 1;
        const int hh  = item & 1;
        float2 hj[12];
        #pragma unroll
        for (int j = 0; j < 12; ++j) hj[j] = hint[blk * 12 + j];
        const int ibase = hh * 6;
        #pragma unroll
        for (int ii = 0; ii < 6; ++ii) {
            const int i = ibase + ii;
            float ar = 0.f, ai = 0.f;
            #pragma unroll
            for (int j = 0; j < 12; ++j) {
                float w = Ws[i * 12 + j];
                ar = fmaf(w, hj[j].x, ar);
                ai = fmaf(w, hj[j].y, ai);
            }
            out[base + blk * 12 + i] = make_float2(ar, ai);
        }
    }
}

// ---------------- launcher ----------------------------------------------------
extern "C" void kernel_launch(void* const* d_in, const int* in_sizes, int n_in,
                              void* d_out, int out_size) {
    const float* lsr = (const float*)d_in[0];
    const float* lsi = (const float*)d_in[1];
    const int*   cs  = (const int*)d_in[2];
    float2* out = (float2*)d_out;

    const int smemA = WTN * 8 + 12 * 8 + 22 * 4;  // 65544 B
    cudaFuncSetAttribute(kA, cudaFuncAttributeMaxDynamicSharedMemorySize, smemA);

    kP<<<(WTN + 255) / 256, 256>>>();
    kA<<<1024, 256, smemA>>>(lsr, lsi, cs);
    kS<<<NUP * NB, 144>>>(cs);
    kB<<<NUP * NB * NA, 256>>>(lsr, lsi, out);
    (void)in_sizes; (void)n_in; (void)out_size;
}

// round 3
// speedup vs baseline: 1.6676x; 1.6676x over previous
#include <cuda_runtime.h>
#include <math.h>

#define LL     1632
#define NUP    8
#define NB     32
#define NA     64
#define RED    408

// ---------------- scratch (device globals) -----------------------------------
__device__ float2 g_phtab[LL];          // e^{2*pi*i*q/L}
__device__ float2 g_b12[12];            // e^{2*pi*i*r/12}
__device__ int    g_m[NUP*NB];          // per (u,b) peak position m
__device__ float  g_Weff[NUP*NB*180];   // per (u,b): 3 classes x 12 x 5
__device__ float  g_win[1024*21];       // per-block partial windows
__device__ float  g_noise[1024];        // per-block partial noise sums

// ---------------- kernel P: tables -------------------------------------------
__global__ void kP() {
    int i = blockIdx.x * blockDim.x + threadIdx.x;
    const double TP = 6.283185307179586476925286766559;
    if (i < LL) {
        double ang = TP * (double)i / (double)LL;
        g_phtab[i] = make_float2((float)cos(ang), (float)sin(ang));
    }
    if (i < 12) {
        double ang = TP * (double)i / 12.0;
        g_b12[i] = make_float2((float)cos(ang), (float)sin(ang));
    }
}

// ---------------- kernel A: 21-bin DFT window power + noise ------------------
__device__ __forceinline__ float wred(float v) {
    #pragma unroll
    for (int off = 16; off; off >>= 1) v += __shfl_xor_sync(0xffffffffu, v, off);
    return v;
}

__global__ __launch_bounds__(256, 2) void kA(const float* __restrict__ lsr,
                                             const float* __restrict__ lsi,
                                             const int*   __restrict__ cs) {
    __shared__ float2 ph[LL];
    __shared__ float  win[22];

    const int tid  = threadIdx.x;
    const int bid  = blockIdx.x;
    const int part = bid & 3;
    const int ub   = bid >> 2;
    const int u    = ub >> 5;

    for (int i = tid; i < LL; i += 256) ph[i] = g_phtab[i];
    if (tid < 22) win[tid] = 0.f;
    __syncthreads();

    int k12 = (12 - (cs[u] % 12)) % 12; if (k12 < 0) k12 += 12;

    const int lane = tid & 31;
    const int warp = tid >> 5;
    const int a0   = part * 16 + warp * 2;
    const int base0 = (ub * 64 + a0) * LL;
    const int base1 = base0 + LL;

    float A0[10], B0[10], C0[10], D0[10];
    float A1[10], B1[10], C1[10], D1[10];
    #pragma unroll
    for (int o = 0; o < 10; ++o) {
        A0[o]=B0[o]=C0[o]=D0[o]=0.f;
        A1[o]=B1[o]=C1[o]=D1[o]=0.f;
    }
    float s0r=0.f, s0i=0.f, s1r=0.f, s1i=0.f, nacc=0.f;

    // base twiddle sequence: index (n*k12)%12 steps by (32*k12)%12 -> period 3
    const int st = (8 * k12) % 12;              // (32*k12) mod 12
    int r = (lane * k12) % 12;
    float2 bb0 = g_b12[r]; r += st; if (r >= 12) r -= 12;
    float2 bb1 = g_b12[r]; r += st; if (r >= 12) r -= 12;
    float2 bb2 = g_b12[r];

    #pragma unroll 3
    for (int k = 0; k < 51; ++k) {
        const int n = lane + (k << 5);
        float x0r = lsr[base0 + n], x0i = lsi[base0 + n];
        float x1r = lsr[base1 + n], x1i = lsi[base1 + n];
        if (n < LL - 1) {
            float d0r = lsr[base0 + n + 1] - x0r, d0i = lsi[base0 + n + 1] - x0i;
            float d1r = lsr[base1 + n + 1] - x1r, d1i = lsi[base1 + n + 1] - x1i;
            nacc += d0r*d0r + d0i*d0i + d1r*d1r + d1i*d1i;
        }
        const int km = k % 3;                    // resolved at compile time (unroll 3)
        float2 b = (km == 0) ? bb0 : ((km == 1) ? bb1 : bb2);

        float g0r = x0r*b.x - x0i*b.y, g0i = fmaf(x0r, b.y, x0i*b.x);
        float g1r = x1r*b.x - x1i*b.y, g1i = fmaf(x1r, b.y, x1i*b.x);
        s0r += g0r; s0i += g0i; s1r += g1r; s1i += g1i;

        const float2 w = ph[n];                  // e^{2*pi*i*n/L}
        float cx = w.x, cy = w.y;                // chirp: e^{2*pi*i*n*(o+1)/L}
        #pragma unroll
        for (int o = 0; o < 10; ++o) {
            A0[o] = fmaf(g0r, cx, A0[o]); B0[o] = fmaf(g0r, cy, B0[o]);
            C0[o] = fmaf(g0i, cx, C0[o]); D0[o] = fmaf(g0i, cy, D0[o]);
            A1[o] = fmaf(g1r, cx, A1[o]); B1[o] = fmaf(g1r, cy, B1[o]);
            C1[o] = fmaf(g1i, cx, C1[o]); D1[o] = fmaf(g1i, cy, D1[o]);
            if (o < 9) {
                float nx = fmaf(cx, w.x, -cy * w.y);
                float ny = fmaf(cx, w.y,  cy * w.x);
                cx = nx; cy = ny;
            }
        }
    }

    #pragma unroll
    for (int o = 0; o < 10; ++o) {
        A0[o]=wred(A0[o]); B0[o]=wred(B0[o]); C0[o]=wred(C0[o]); D0[o]=wred(D0[o]);
        A1[o]=wred(A1[o]); B1[o]=wred(B1[o]); C1[o]=wred(C1[o]); D1[o]=wred(D1[o]);
    }
    s0r=wred(s0r); s0i=wred(s0i); s1r=wred(s1r); s1i=wred(s1i); nacc=wred(nacc);

    if (lane == 0) {
        atomicAdd(&win[10], s0r*s0r + s0i*s0i + s1r*s1r + s1i*s1i);
        #pragma unroll
        for (int o = 0; o < 10; ++o) {
            float rp0 = A0[o]-D0[o], ip0 = B0[o]+C0[o];
            float rp1 = A1[o]-D1[o], ip1 = B1[o]+C1[o];
            atomicAdd(&win[11+o], rp0*rp0 + ip0*ip0 + rp1*rp1 + ip1*ip1);
            float rm0 = A0[o]+D0[o], im0 = C0[o]-B0[o];
            float rm1 = A1[o]+D1[o], im1 = C1[o]-B1[o];
            atomicAdd(&win[9-o],  rm0*rm0 + im0*im0 + rm1*rm1 + im1*im1);
        }
        atomicAdd(&win[21], nacc);
    }
    __syncthreads();
    if (tid < 21) g_win[bid * 21 + tid] = win[tid];
    if (tid == 21) g_noise[bid] = win[21];
}

// ---------------- kernel S: argmax + Wiener solve + Weff ---------------------
__global__ void kS(const int* __restrict__ cs) {
    __shared__ float win[21];
    __shared__ float Cm[144], Am[144], Iv[144], Wsh[144];
    __shared__ float s_sh;

    const int ub = blockIdx.x;
    const int tid = threadIdx.x;           // 144 threads
    const int u = ub >> 5;
    const int i = tid / 12, j = tid % 12;

    if (tid < 21) {
        float s = 0.f;
        #pragma unroll
        for (int p = 0; p < 4; ++p) s += g_win[(ub * 4 + p) * 21 + tid];
        win[tid] = s;
    }
    if (tid == 21) {
        float s = 0.f;
        #pragma unroll
        for (int p = 0; p < 4; ++p) s += g_noise[ub * 4 + p];
        s_sh = s / (64.0f * 1631.0f * 2.0f);
    }
    __syncthreads();

    if (tid == 0) {
        int bi = 0; float bv = win[0];
        for (int q = 1; q < 21; ++q) if (win[q] > bv) { bv = win[q]; bi = q; }
        int k12 = (12 - (cs[u] % 12)) % 12; if (k12 < 0) k12 += 12;
        g_m[ub] = k12 * 136 + (bi - 10);
    }

    int d = i - j; if (d < 0) d = -d;
    float c = (float)pow(0.9, (double)d);
    Cm[tid] = c;
    Am[tid] = c + ((i == j) ? s_sh : 0.f);
    Iv[tid] = (i == j) ? 1.f : 0.f;
    __syncthreads();

    for (int k = 0; k < 12; ++k) {
        float piv = Am[k * 12 + k];
        __syncthreads();
        if (i == k) {
            float ip = 1.0f / piv;
            Am[tid] *= ip; Iv[tid] *= ip;
        }
        __syncthreads();
        float f   = Am[i * 12 + k];
        float akj = Am[k * 12 + j];
        float ikj = Iv[k * 12 + j];
        __syncthreads();
        if (i != k) {
            Am[tid] = fmaf(-f, akj, Am[tid]);
            Iv[tid] = fmaf(-f, ikj, Iv[tid]);
        }
        __syncthreads();
    }

    float w = 0.f;
    #pragma unroll
    for (int k2 = 0; k2 < 12; ++k2) w = fmaf(Cm[i * 12 + k2], Iv[k2 * 12 + j], w);
    Wsh[tid] = w;
    __syncthreads();

    // Weff[class][i][s] = sum_j W[i][j] * Lerp[class][j][s]
    for (int item = tid; item < 180; item += 144) {
        const int cl  = item / 60;
        const int rem = item - cl * 60;
        const int ii  = rem / 5;
        const int s   = rem - ii * 5;
        const int rep = (cl == 0) ? 0 : ((cl == 1) ? 1 : 135);
        const int hb  = 3 * rep - 1;
        float acc = 0.f;
        #pragma unroll
        for (int jj = 0; jj < 12; ++jj) {
            float t = (float)(rep * 12 + jj);
            float p = (t - 1.5f) * 0.25f;
            p = fminf(fmaxf(p, 0.f), 407.f);
            int i0 = (int)p; if (i0 > 406) i0 = 406;
            float fr = p - (float)i0;
            int s0 = i0 - hb;
            float coef = (s == s0) ? (1.f - fr) : ((s == s0 + 1) ? fr : 0.f);
            acc = fmaf(Wsh[ii * 12 + jj], coef, acc);
        }
        g_Weff[ub * 180 + item] = acc;
    }
}

// ---------------- kernel B: phase + 4-avg + (interp*W folded) ----------------
__global__ __launch_bounds__(256) void kB(const float* __restrict__ lsr,
                                          const float* __restrict__ lsi,
                                          float2* __restrict__ out) {
    __shared__ float2 ph[LL];
    __shared__ float2 havg[4 * RED];
    __shared__ float  We[180];

    const int tid  = threadIdx.x;
    const int row0 = blockIdx.x * 4;      // 4 rows, same ub (64 rows per ub)
    const int ub   = row0 >> 6;

    if (tid < 180) We[tid] = g_Weff[ub * 180 + tid];
    const int m  = g_m[ub];
    const int mm = ((m % LL) + LL) % LL;

    for (int n = tid; n < LL; n += 256) ph[n] = g_phtab[(n * mm) % LL];
    __syncthreads();

    // stage 1: phase-shifted 4-tap average
    for (int item = tid; item < 4 * RED; item += 256) {
        const int rl = item / RED;
        const int rr = item - rl * RED;
        const int base = (row0 + rl) * LL + 4 * rr;
        const float4 xr = *(const float4*)(lsr + base);
        const float4 xi = *(const float4*)(lsi + base);
        const float2 p0 = ph[4*rr], p1 = ph[4*rr+1], p2 = ph[4*rr+2], p3 = ph[4*rr+3];
        float sr, si;
        sr = xr.x * p0.x;              si = xr.x * p0.y;
        sr = fmaf(-xi.x, p0.y, sr);    si = fmaf( xi.x, p0.x, si);
        sr = fmaf( xr.y, p1.x, sr);    si = fmaf( xr.y, p1.y, si);
        sr = fmaf(-xi.y, p1.y, sr);    si = fmaf( xi.y, p1.x, si);
        sr = fmaf( xr.z, p2.x, sr);    si = fmaf( xr.z, p2.y, si);
        sr = fmaf(-xi.z, p2.y, sr);    si = fmaf( xi.z, p2.x, si);
        sr = fmaf( xr.w, p3.x, sr);    si = fmaf( xr.w, p3.y, si);
        sr = fmaf(-xi.w, p3.y, sr);    si = fmaf( xi.w, p3.x, si);
        havg[rl * RED + rr] = make_float2(sr * 0.25f, si * 0.25f);
    }
    __syncthreads();

    // stage 2: 5-tap effective stencil (interp + W folded)
    for (int item = tid; item < 4 * LL; item += 256) {
        const int rl = item / LL;
        const int t  = item - rl * LL;
        const int blk = t / 12;
        const int i   = t - blk * 12;
        const int cl  = (blk == 0) ? 0 : ((blk == 135) ? 2 : 1);
        const float* w = &We[cl * 60 + i * 5];
        const int hb = 3 * blk - 1;
        const int hbase = rl * RED;
        float ar = 0.f, ai = 0.f;
        #pragma unroll
        for (int s = 0; s < 5; ++s) {
            int idx = hb + s;
            idx = (idx < 0) ? 0 : ((idx > RED - 1) ? RED - 1 : idx);
            const float2 h = havg[hbase + idx];
            const float ww = w[s];
            ar = fmaf(ww, h.x, ar);
            ai = fmaf(ww, h.y, ai);
        }
        out[(row0 + rl) * LL + t] = make_float2(ar, ai);
    }
}

// ---------------- launcher ----------------------------------------------------
extern "C" void kernel_launch(void* const* d_in, const int* in_sizes, int n_in,
                              void* d_out, int out_size) {
    const float* lsr = (const float*)d_in[0];
    const float* lsi = (const float*)d_in[1];
    const int*   cs  = (const int*)d_in[2];
    float2* out = (float2*)d_out;

    kP<<<7, 256>>>();
    kA<<<1024, 256>>>(lsr, lsi, cs);
    kS<<<NUP * NB, 144>>>(cs);
    kB<<<NUP * NB * NA / 4, 256>>>(lsr, lsi, out);
    (void)in_sizes; (void)n_in; (void)out_size;
}